// round 5
// baseline (speedup 1.0000x reference)
#include <cuda_runtime.h>

// PhonologicalLoopMemory — minimal-traffic, balance-tuned.
//   out[b] = concat(recent[0..3], rehearsal), segment = 32768 f32 = 8192 float4.
//   recent[0] = rehearsal = features[b]   (buf[old_pos] just set -> undecayed)
//   recent[j] = valid_j ? 0.9 * feature_buffer[b, (pos[b]-j) & 63] : 0, j=1..3
//   valid_j = buffer_filled[b] || (j <= pos[b])
//
// Traffic floor: 72 MiB (LTS-cap bound ~6.3 TB/s). Heavy tiles (1R+2W) scheduled
// first via low blockIdx; UNROLL=4 for finer balance quantum + higher occupancy.

#define SEG_F4   8192   // 32768 floats / 4
#define BUF_LEN  64
#define NSEG     5
#define UNROLL   4
#define TPB      256
#define TILE_F4  (TPB * UNROLL)          // 1024 float4 per tile
#define XT       (SEG_F4 / TILE_F4)      // 8 x-tiles per segment
#define N_HEAVY  (64 * XT)               // 512 j0 tiles (1R + 2W)

__global__ __launch_bounds__(TPB) void phono_kernel(
    const float4* __restrict__ feat,          // [B, 8192]
    const float4* __restrict__ fbuf,          // [B, 64, 8192]
    const int*    __restrict__ cur_pos,       // [B]
    const int*    __restrict__ filled,        // [B] int32 (bool upcast)
    float4* __restrict__ out)                 // [B, 5, 8192]
{
    const int bid = blockIdx.x;
    float4 v[UNROLL];

    if (bid < N_HEAVY) {
        // features -> recent[0] (seg 0) AND rehearsal (seg 4): one read, two writes.
        const int b    = bid >> 3;            // bid / XT
        const int x    = bid & (XT - 1);
        const int base = x * TILE_F4 + threadIdx.x;

        const float4* src = feat + (size_t)b * SEG_F4 + base;
        #pragma unroll
        for (int k = 0; k < UNROLL; k++) v[k] = src[k * TPB];

        float4* dst0 = out + ((size_t)b * NSEG + 0) * SEG_F4 + base;
        float4* dst4 = out + ((size_t)b * NSEG + 4) * SEG_F4 + base;
        #pragma unroll
        for (int k = 0; k < UNROLL; k++) dst0[k * TPB] = v[k];
        #pragma unroll
        for (int k = 0; k < UNROLL; k++) dst4[k * TPB] = v[k];
        return;
    }

    // Light tiles: segments j = 1..3 (1 read + 1 write).
    const int t    = bid - N_HEAVY;           // 0 .. 64*3*XT-1
    const int seg  = t >> 3;                  // b*3 + (j-1)
    const int x    = t & (XT - 1);
    const int b    = seg / 3;
    const int j    = seg - b * 3 + 1;
    const int base = x * TILE_F4 + threadIdx.x;

    const int p = cur_pos[b];
    const bool valid = (filled[b] != 0) || (j <= p);
    if (valid) {
        const int slot = (p - j + BUF_LEN) & (BUF_LEN - 1);
        const float4* src = fbuf + ((size_t)b * BUF_LEN + slot) * SEG_F4 + base;
        #pragma unroll
        for (int k = 0; k < UNROLL; k++) v[k] = src[k * TPB];
        #pragma unroll
        for (int k = 0; k < UNROLL; k++) {
            v[k].x *= 0.9f; v[k].y *= 0.9f; v[k].z *= 0.9f; v[k].w *= 0.9f;
        }
    } else {
        #pragma unroll
        for (int k = 0; k < UNROLL; k++) v[k] = make_float4(0.f, 0.f, 0.f, 0.f);
    }

    float4* dst = out + ((size_t)b * NSEG + j) * SEG_F4 + base;
    #pragma unroll
    for (int k = 0; k < UNROLL; k++) dst[k * TPB] = v[k];
}

extern "C" void kernel_launch(void* const* d_in, const int* in_sizes, int n_in,
                              void* d_out, int out_size)
{
    const float4* feat   = (const float4*)d_in[0];
    const float4* fbuf   = (const float4*)d_in[1];
    const int*    pos    = (const int*)d_in[2];
    const int*    filled = (const int*)d_in[3];
    float4*       out    = (float4*)d_out;

    const int total_blocks = N_HEAVY + 64 * 3 * XT;   // 512 + 1536 = 2048
    phono_kernel<<<total_blocks, TPB>>>(feat, fbuf, pos, filled, out);
}

// round 7
// speedup vs baseline: 1.0201x; 1.0201x over previous
#include <cuda_runtime.h>

// PhonologicalLoopMemory — minimal-traffic + L2-resident (evict_last, 256-bit) form.
//   out[b] = concat(recent[0..3], rehearsal), segment = 32768 f32.
//   recent[0] = rehearsal = features[b]   (buf[old_pos] just set -> undecayed)
//   recent[j] = valid_j ? 0.9 * feature_buffer[b, (pos[b]-j) & 63] : 0, j=1..3
//   valid_j = buffer_filled[b] || (j <= pos[b])
//
// sm_103 ptxas requires .v4.b64 (32B) with .L2::evict_last -> 256-bit accesses.
// Working set 72 MiB < 126 MB L2: pin reads AND writes so dirty out lines are
// overwritten in place across graph replays (no DRAM writeback/refill).

#define SEG_U    4096   // segment in 32B units (32768 f32 * 4B / 32B)
#define BUF_LEN  64
#define NSEG     5
#define UNROLL   4
#define TPB      256

typedef unsigned long long u64;
union V32 { struct { u64 a, b, c, d; } u; float f[8]; };

__device__ __forceinline__ void ld_evl(const void* p, V32& v) {
    asm volatile("ld.global.L2::evict_last.v4.b64 {%0,%1,%2,%3}, [%4];"
                 : "=l"(v.u.a), "=l"(v.u.b), "=l"(v.u.c), "=l"(v.u.d) : "l"(p));
}
__device__ __forceinline__ void st_evl(void* p, const V32& v) {
    asm volatile("st.global.L2::evict_last.v4.b64 [%0], {%1,%2,%3,%4};"
                 :: "l"(p), "l"(v.u.a), "l"(v.u.b), "l"(v.u.c), "l"(v.u.d)
                 : "memory");
}

__global__ __launch_bounds__(TPB) void phono_kernel(
    const char* __restrict__ feat,            // [B] segments of 128 KB
    const char* __restrict__ fbuf,            // [B, 64] segments of 128 KB
    const int*  __restrict__ cur_pos,         // [B]
    const int*  __restrict__ filled,          // [B] int32 (bool upcast)
    char* __restrict__ out)                   // [B, 5] segments of 128 KB
{
    const int by   = blockIdx.y;              // b*4 + j, j in 0..3 (j==0 covers segs 0 and 4)
    const int b    = by >> 2;
    const int j    = by & 3;
    const size_t base = ((size_t)blockIdx.x * (TPB * UNROLL) + threadIdx.x) * 32;  // bytes

    V32 v[UNROLL];
    char* dst0 = out + ((size_t)b * NSEG + j) * (SEG_U * 32) + base;

    if (j == 0) {
        // features -> recent[0] AND rehearsal (seg 4): one read, two writes.
        const char* src = feat + (size_t)b * (SEG_U * 32) + base;
        #pragma unroll
        for (int k = 0; k < UNROLL; k++) ld_evl(src + k * (TPB * 32), v[k]);

        char* dst4 = out + ((size_t)b * NSEG + 4) * (SEG_U * 32) + base;
        #pragma unroll
        for (int k = 0; k < UNROLL; k++) st_evl(dst0 + k * (TPB * 32), v[k]);
        #pragma unroll
        for (int k = 0; k < UNROLL; k++) st_evl(dst4 + k * (TPB * 32), v[k]);
        return;
    }

    const int p = cur_pos[b];
    const bool valid = (filled[b] != 0) || (j <= p);
    if (valid) {
        const int slot = (p - j + BUF_LEN) & (BUF_LEN - 1);
        const char* src = fbuf + ((size_t)b * BUF_LEN + slot) * (SEG_U * 32) + base;
        #pragma unroll
        for (int k = 0; k < UNROLL; k++) ld_evl(src + k * (TPB * 32), v[k]);
        #pragma unroll
        for (int k = 0; k < UNROLL; k++)
            #pragma unroll
            for (int e = 0; e < 8; e++) v[k].f[e] *= 0.9f;
    } else {
        #pragma unroll
        for (int k = 0; k < UNROLL; k++)
            #pragma unroll
            for (int e = 0; e < 8; e++) v[k].f[e] = 0.f;
    }
    #pragma unroll
    for (int k = 0; k < UNROLL; k++) st_evl(dst0 + k * (TPB * 32), v[k]);
}

extern "C" void kernel_launch(void* const* d_in, const int* in_sizes, int n_in,
                              void* d_out, int out_size)
{
    const char* feat   = (const char*)d_in[0];
    const char* fbuf   = (const char*)d_in[1];
    const int*  pos    = (const int*)d_in[2];
    const int*  filled = (const int*)d_in[3];
    char*       out    = (char*)d_out;

    const int batch = in_sizes[2];                    // 64
    dim3 block(TPB);
    dim3 grid(SEG_U / (TPB * UNROLL), batch * 4);     // (4, 256) = 1024 blocks
    phono_kernel<<<grid, block>>>(feat, fbuf, pos, filled, out);
}